// round 6
// baseline (speedup 1.0000x reference)
#include <cuda_runtime.h>
#include <cstdint>

#define NN 50000
#define NE 800000

// ---------------- device scratch ----------------
__device__ int   g_rowstart[NN + 1];
__device__ int   g_cursor[NN];
__device__ int2  g_edge[NE];                    // {src, w_bits} packed
__device__ float g_aggx[(size_t)NN * 96];       // gconv(x) all (f,t): col = f*12+t
__device__ float g_h0[(size_t)NN * 64];
__device__ float g_h1[(size_t)NN * 64];
__device__ float g_rh[(size_t)NN * 64];         // r*h scratch
__device__ float g_z [(size_t)NN * 64];         // z scratch
__device__ float g_aggh0[(size_t)NN * 64];      // agg(h0) saved by L1 gate for L1 cand

// ---------------- init ----------------
__global__ void k_init() {
    int i = blockIdx.x * blockDim.x + threadIdx.x;
    size_t tot = (size_t)NN * 64;
    if ((size_t)i < tot) { g_h0[i] = 0.f; g_h1[i] = 0.f; }
    if (i < NN) g_cursor[i] = 0;
}

__global__ void k_count(const int* __restrict__ dst, int E) {
    int i = blockIdx.x * blockDim.x + threadIdx.x;
    if (i < E) atomicAdd(&g_cursor[dst[i]], 1);
}

__global__ void k_scan() {
    __shared__ int sums[1024];
    int tid = threadIdx.x;
    const int CH = (NN + 1023) / 1024;
    int base = tid * CH;
    int s = 0;
    for (int i = 0; i < CH; i++) {
        int idx = base + i;
        if (idx < NN) s += g_cursor[idx];
    }
    sums[tid] = s;
    __syncthreads();
    for (int off = 1; off < 1024; off <<= 1) {
        int v = 0;
        if (tid >= off) v = sums[tid - off];
        __syncthreads();
        sums[tid] += v;
        __syncthreads();
    }
    int run = (tid == 0) ? 0 : sums[tid - 1];
    for (int i = 0; i < CH; i++) {
        int idx = base + i;
        if (idx < NN) {
            int c = g_cursor[idx];
            g_rowstart[idx] = run;
            g_cursor[idx]   = run;
            run += c;
        }
    }
    if (tid == 0) g_rowstart[NN] = sums[1023];
}

__global__ void k_scatter(const int* __restrict__ src, const int* __restrict__ dst,
                          const float* __restrict__ w, int E) {
    int i = blockIdx.x * blockDim.x + threadIdx.x;
    if (i < E) {
        int d = dst[i];
        int p = atomicAdd(&g_cursor[d], 1);
        g_edge[p] = make_int2(src[i], __float_as_int(w[i]));
    }
}

// ---------------- aggx: warp per node, uniform edge loads ----------------
__global__ void k_aggx(const float* __restrict__ x) {
    int n = (blockIdx.x * blockDim.x + threadIdx.x) >> 5;
    int lane = threadIdx.x & 31;
    if (n >= NN) return;
    int s0 = g_rowstart[n], s1 = g_rowstart[n + 1];
    float a0 = 0.f, a1 = 0.f, a2 = 0.f;
    #pragma unroll 4
    for (int e = s0; e < s1; e++) {
        int2 ed = g_edge[e];
        float w = __int_as_float(ed.y);
        const float* fp = x + (size_t)ed.x * 96;
        a0 += w * fp[lane];
        a1 += w * fp[lane + 32];
        a2 += w * fp[lane + 64];
    }
    float* op = g_aggx + (size_t)n * 96;
    op[lane] = a0; op[lane + 32] = a1; op[lane + 64] = a2;
}

// ---------------- fused gather + GEMM + gate/candidate epilogue ----------------
// MODE 0: L0 gate  (A=[x@t | agg(h0)], K=72,  NOUT=128): rh=sig(r)*h0, z=sig(z)
// MODE 1: L0 cand  (A=[x@t | agg(rh)], K=72,  NOUT=64):  h0 = z*h0+(1-z)*tanh(.)
// MODE 2: L1 gate  (A=[agg(h0)|agg(h1)], K=128, NOUT=128): also saves agg(h0)->g_aggh0
// MODE 3: L1 cand  (A=[g_aggh0|agg(rh)], K=128, NOUT=64):  h1 update
__device__ __forceinline__ float fsig(float x)  { return 1.f / (1.f + __expf(-x)); }
__device__ __forceinline__ float ftanh(float x) { return 2.f / (1.f + __expf(-2.f * x)) - 1.f; }

template<int MODE>
__global__ void __launch_bounds__(256) k_fused(const float* __restrict__ W,
                                               const float* __restrict__ B, int t) {
    constexpr int  K    = (MODE < 2) ? 72 : 128;
    constexpr int  KP   = (MODE < 2) ? 96 : 128;   // padded to multiple of 32
    constexpr bool GATE = (MODE == 0 || MODE == 2);
    constexpr int  NOUT = GATE ? 128 : 64;
    constexpr int  LDA  = 134;                     // pad: 8B-aligned pairs, <=4-way STS
    extern __shared__ float sm[];
    float* As = sm;                                // [KP][LDA] transposed A tile
    float* Ws = sm + KP * LDA;                     // [32][64] streamed W tile

    int tid  = threadIdx.x;
    int lane = tid & 31;
    int wid  = tid >> 5;
    int rowBlock = blockIdx.x * 128;
    float* __restrict__ h = (MODE < 2) ? g_h0 : g_h1;

    // zero the K..KP pad rows (they participate in the last K-tile)
    if (KP > K) {
        for (int i = tid; i < (KP - K) * LDA; i += 256) As[K * LDA + i] = 0.f;
    }

    // ---- gather phase: warp per node, 16 nodes per warp ----
    for (int rr = 0; rr < 16; rr++) {
        int r = wid * 16 + rr;
        int n = rowBlock + r;
        if (n >= NN) continue;
        int s0 = g_rowstart[n], s1 = g_rowstart[n + 1];
        if (MODE == 0 || MODE == 1) {
            const float* __restrict__ feat = (MODE == 0) ? g_h0 : g_rh;
            float a0 = 0.f, a1 = 0.f;
            #pragma unroll 4
            for (int e = s0; e < s1; e++) {
                int2 ed = g_edge[e];
                float w = __int_as_float(ed.y);
                float2 v = *reinterpret_cast<const float2*>(feat + (size_t)ed.x * 64 + 2 * lane);
                a0 += w * v.x; a1 += w * v.y;
            }
            As[(8 + 2 * lane) * LDA + r] = a0;
            As[(9 + 2 * lane) * LDA + r] = a1;
            if (lane < 8) As[lane * LDA + r] = g_aggx[(size_t)n * 96 + lane * 12 + t];
        } else if (MODE == 2) {
            float a0 = 0.f, a1 = 0.f, a2 = 0.f, a3 = 0.f;
            #pragma unroll 4
            for (int e = s0; e < s1; e++) {
                int2 ed = g_edge[e];
                float w = __int_as_float(ed.y);
                float2 v0 = *reinterpret_cast<const float2*>(g_h0 + (size_t)ed.x * 64 + 2 * lane);
                float2 v1 = *reinterpret_cast<const float2*>(g_h1 + (size_t)ed.x * 64 + 2 * lane);
                a0 += w * v0.x; a1 += w * v0.y;
                a2 += w * v1.x; a3 += w * v1.y;
            }
            As[(2 * lane)      * LDA + r] = a0;
            As[(2 * lane + 1)  * LDA + r] = a1;
            As[(64 + 2 * lane) * LDA + r] = a2;
            As[(65 + 2 * lane) * LDA + r] = a3;
            *reinterpret_cast<float2*>(g_aggh0 + (size_t)n * 64 + 2 * lane) = make_float2(a0, a1);
        } else { // MODE 3
            float2 c = *reinterpret_cast<const float2*>(g_aggh0 + (size_t)n * 64 + 2 * lane);
            As[(2 * lane)     * LDA + r] = c.x;
            As[(2 * lane + 1) * LDA + r] = c.y;
            float a0 = 0.f, a1 = 0.f;
            #pragma unroll 4
            for (int e = s0; e < s1; e++) {
                int2 ed = g_edge[e];
                float w = __int_as_float(ed.y);
                float2 v = *reinterpret_cast<const float2*>(g_rh + (size_t)ed.x * 64 + 2 * lane);
                a0 += w * v.x; a1 += w * v.y;
            }
            As[(64 + 2 * lane) * LDA + r] = a0;
            As[(65 + 2 * lane) * LDA + r] = a1;
        }
    }
    __syncthreads();

    // ---- GEMM phase ----
    int rg = tid >> 4, cg = tid & 15;
    int r0 = rg * 8, c0 = cg * 4;
    constexpr int NY = GATE ? 2 : 1;

    for (int ycol = 0; ycol < NY; ycol++) {
        int colBlock = ycol * 64;
        unsigned long long acc[4][4];
        #pragma unroll
        for (int p = 0; p < 4; p++)
            #pragma unroll
            for (int q = 0; q < 4; q++) acc[p][q] = 0ull;

        for (int kc = 0; kc < KP; kc += 32) {
            // stream the 32 x 64 W tile
            #pragma unroll
            for (int l = 0; l < 8; l++) {
                int idx = tid + l * 256;          // 0..2047
                int kk = idx >> 6, j = idx & 63;
                int gk = kc + kk;
                Ws[kk * 64 + j] = (gk < K) ? W[(size_t)gk * NOUT + colBlock + j] : 0.f;
            }
            __syncthreads();
            #pragma unroll
            for (int kk = 0; kk < 32; kk++) {
                float4 b = *reinterpret_cast<const float4*>(&Ws[kk * 64 + c0]);
                unsigned long long bd[4];
                asm("mov.b64 %0,{%1,%1};" : "=l"(bd[0]) : "f"(b.x));
                asm("mov.b64 %0,{%1,%1};" : "=l"(bd[1]) : "f"(b.y));
                asm("mov.b64 %0,{%1,%1};" : "=l"(bd[2]) : "f"(b.z));
                asm("mov.b64 %0,{%1,%1};" : "=l"(bd[3]) : "f"(b.w));
                unsigned long long ap[4];
                #pragma unroll
                for (int p = 0; p < 4; p++)
                    ap[p] = *reinterpret_cast<const unsigned long long*>(
                        &As[(kc + kk) * LDA + r0 + 2 * p]);
                #pragma unroll
                for (int p = 0; p < 4; p++)
                    #pragma unroll
                    for (int q = 0; q < 4; q++)
                        asm("fma.rn.f32x2 %0,%1,%2,%0;" : "+l"(acc[p][q]) : "l"(ap[p]), "l"(bd[q]));
            }
            __syncthreads();
        }

        float bias[4];
        #pragma unroll
        for (int q = 0; q < 4; q++) bias[q] = B[colBlock + c0 + q];

        #pragma unroll
        for (int p = 0; p < 4; p++) {
            float vlo[4], vhi[4];
            #pragma unroll
            for (int q = 0; q < 4; q++)
                asm("mov.b64 {%0,%1},%2;" : "=f"(vlo[q]), "=f"(vhi[q]) : "l"(acc[p][q]));
            #pragma unroll
            for (int hp = 0; hp < 2; hp++) {
                int n = rowBlock + r0 + 2 * p + hp;
                if (n >= NN) continue;
                float v[4];
                #pragma unroll
                for (int q = 0; q < 4; q++) v[q] = (hp ? vhi[q] : vlo[q]) + bias[q];
                if (GATE) {
                    if (ycol == 0) {
                        float4 h4 = *reinterpret_cast<const float4*>(&h[(size_t)n * 64 + c0]);
                        float4 o = make_float4(fsig(v[0]) * h4.x, fsig(v[1]) * h4.y,
                                               fsig(v[2]) * h4.z, fsig(v[3]) * h4.w);
                        *reinterpret_cast<float4*>(&g_rh[(size_t)n * 64 + c0]) = o;
                    } else {
                        float4 o = make_float4(fsig(v[0]), fsig(v[1]), fsig(v[2]), fsig(v[3]));
                        *reinterpret_cast<float4*>(&g_z[(size_t)n * 64 + c0]) = o;
                    }
                } else {
                    float4 z4 = *reinterpret_cast<const float4*>(&g_z[(size_t)n * 64 + c0]);
                    float4 h4 = *reinterpret_cast<const float4*>(&h[(size_t)n * 64 + c0]);
                    float4 o = make_float4(z4.x * h4.x + (1.f - z4.x) * ftanh(v[0]),
                                           z4.y * h4.y + (1.f - z4.y) * ftanh(v[1]),
                                           z4.z * h4.z + (1.f - z4.z) * ftanh(v[2]),
                                           z4.w * h4.w + (1.f - z4.w) * ftanh(v[3]));
                    *reinterpret_cast<float4*>(&h[(size_t)n * 64 + c0]) = o;
                }
            }
        }
    }
}

// ---------------- output head ----------------
__global__ void k_out(const float* __restrict__ Wout, const float* __restrict__ bout,
                      float* __restrict__ out) {
    int n = (blockIdx.x * blockDim.x + threadIdx.x) >> 5;
    int lane = threadIdx.x & 31;
    if (n >= NN) return;
    const float* hp = g_h1 + (size_t)n * 64;
    float s = hp[lane] * Wout[lane] + hp[lane + 32] * Wout[lane + 32];
    #pragma unroll
    for (int off = 16; off > 0; off >>= 1)
        s += __shfl_down_sync(0xffffffffu, s, off);
    if (lane == 0) out[n] = s + bout[0];
}

// ---------------- host launcher ----------------
extern "C" void kernel_launch(void* const* d_in, const int* in_sizes, int n_in,
                              void* d_out, int out_size) {
    const float* x    = (const float*)d_in[0];
    const int*   ei   = (const int*)  d_in[1];
    const float* ew   = (const float*)d_in[2];
    const float* Wg0  = (const float*)d_in[3];
    const float* bg0  = (const float*)d_in[4];
    const float* Wc0  = (const float*)d_in[5];
    const float* bc0  = (const float*)d_in[6];
    const float* Wg1  = (const float*)d_in[7];
    const float* bg1  = (const float*)d_in[8];
    const float* Wc1  = (const float*)d_in[9];
    const float* bc1  = (const float*)d_in[10];
    const float* Wout = (const float*)d_in[11];
    const float* bout = (const float*)d_in[12];

    int E = in_sizes[1] / 2;
    if (E > NE) E = NE;
    const int* src = ei;
    const int* dst = ei + E;

    // dynamic smem sizes
    const int SMEM_L0 = (96 * 134 + 32 * 64) * 4;    // 59648 B
    const int SMEM_L1 = (128 * 134 + 32 * 64) * 4;   // 76800 B
    cudaFuncSetAttribute(k_fused<0>, cudaFuncAttributeMaxDynamicSharedMemorySize, SMEM_L0);
    cudaFuncSetAttribute(k_fused<1>, cudaFuncAttributeMaxDynamicSharedMemorySize, SMEM_L0);
    cudaFuncSetAttribute(k_fused<2>, cudaFuncAttributeMaxDynamicSharedMemorySize, SMEM_L1);
    cudaFuncSetAttribute(k_fused<3>, cudaFuncAttributeMaxDynamicSharedMemorySize, SMEM_L1);

    {
        size_t tot = (size_t)NN * 64;
        k_init<<<(int)((tot + 255) / 256), 256>>>();
    }
    k_count<<<(E + 255) / 256, 256>>>(dst, E);
    k_scan<<<1, 1024>>>();
    k_scatter<<<(E + 255) / 256, 256>>>(src, dst, ew, E);

    const int AGG_BLOCKS = (NN + 7) / 8;
    k_aggx<<<AGG_BLOCKS, 256>>>(x);

    const int GM = (NN + 127) / 128;   // 391 blocks

    for (int t = 0; t < 12; t++) {
        k_fused<0><<<GM, 256, SMEM_L0>>>(Wg0, bg0, t);
        k_fused<1><<<GM, 256, SMEM_L0>>>(Wc0, bc0, t);
        k_fused<2><<<GM, 256, SMEM_L1>>>(Wg1, bg1, t);
        k_fused<3><<<GM, 256, SMEM_L1>>>(Wc1, bc1, t);
    }

    k_out<<<AGG_BLOCKS, 256>>>(Wout, bout, (float*)d_out);
}

// round 7
// speedup vs baseline: 1.2037x; 1.2037x over previous
#include <cuda_runtime.h>
#include <cstdint>

#define NN 50000
#define NE 800000
#define NTILES 782          // ceil(NN/64)
#define GRID_F 391          // blocks per fused launch; each does 2 tiles

// ---------------- device scratch ----------------
__device__ int   g_rowstart[NN + 1];
__device__ int   g_cursor[NN];
__device__ int2  g_edge[NE];                    // {src, w_bits} packed
__device__ float g_aggx[(size_t)NN * 96];       // gconv(x) all (f,t): col = f*12+t
__device__ float g_h0[(size_t)NN * 64];
__device__ float g_h1[(size_t)NN * 64];
__device__ float g_rh[(size_t)NN * 64];         // r*h scratch
__device__ float g_z [(size_t)NN * 64];         // z scratch
__device__ float g_aggh0[(size_t)NN * 64];      // agg(h0) saved by L1 gate for L1 cand

// ---------------- init ----------------
__global__ void k_init() {
    int i = blockIdx.x * blockDim.x + threadIdx.x;
    size_t tot = (size_t)NN * 64;
    if ((size_t)i < tot) { g_h0[i] = 0.f; g_h1[i] = 0.f; }
    if (i < NN) g_cursor[i] = 0;
}

__global__ void k_count(const int* __restrict__ dst, int E) {
    int i = blockIdx.x * blockDim.x + threadIdx.x;
    if (i < E) atomicAdd(&g_cursor[dst[i]], 1);
}

__global__ void k_scan() {
    __shared__ int sums[1024];
    int tid = threadIdx.x;
    const int CH = (NN + 1023) / 1024;
    int base = tid * CH;
    int s = 0;
    for (int i = 0; i < CH; i++) {
        int idx = base + i;
        if (idx < NN) s += g_cursor[idx];
    }
    sums[tid] = s;
    __syncthreads();
    for (int off = 1; off < 1024; off <<= 1) {
        int v = 0;
        if (tid >= off) v = sums[tid - off];
        __syncthreads();
        sums[tid] += v;
        __syncthreads();
    }
    int run = (tid == 0) ? 0 : sums[tid - 1];
    for (int i = 0; i < CH; i++) {
        int idx = base + i;
        if (idx < NN) {
            int c = g_cursor[idx];
            g_rowstart[idx] = run;
            g_cursor[idx]   = run;
            run += c;
        }
    }
    if (tid == 0) g_rowstart[NN] = sums[1023];
}

__global__ void k_scatter(const int* __restrict__ src, const int* __restrict__ dst,
                          const float* __restrict__ w, int E) {
    int i = blockIdx.x * blockDim.x + threadIdx.x;
    if (i < E) {
        int d = dst[i];
        int p = atomicAdd(&g_cursor[d], 1);
        g_edge[p] = make_int2(src[i], __float_as_int(w[i]));
    }
}

// ---------------- aggx: warp per node, uniform edge loads ----------------
__global__ void k_aggx(const float* __restrict__ x) {
    int n = (blockIdx.x * blockDim.x + threadIdx.x) >> 5;
    int lane = threadIdx.x & 31;
    if (n >= NN) return;
    int s0 = g_rowstart[n], s1 = g_rowstart[n + 1];
    float a0 = 0.f, a1 = 0.f, a2 = 0.f;
    #pragma unroll 4
    for (int e = s0; e < s1; e++) {
        int2 ed = g_edge[e];
        float w = __int_as_float(ed.y);
        const float* fp = x + (size_t)ed.x * 96;
        a0 += w * fp[lane];
        a1 += w * fp[lane + 32];
        a2 += w * fp[lane + 64];
    }
    float* op = g_aggx + (size_t)n * 96;
    op[lane] = a0; op[lane + 32] = a1; op[lane + 64] = a2;
}

// ---------------- fused gather + GEMM + gate/candidate epilogue (BM=64) ----------------
// MODE 0: L0 gate  (A=[x@t | agg(h0)], K=72,  NOUT=128): rh=sig(r)*h0, z=sig(z)
// MODE 1: L0 cand  (A=[x@t | agg(rh)], K=72,  NOUT=64):  h0 = z*h0+(1-z)*tanh(.)
// MODE 2: L1 gate  (A=[agg(h0)|agg(h1)], K=128, NOUT=128): also saves agg(h0)->g_aggh0
// MODE 3: L1 cand  (A=[g_aggh0|agg(rh)], K=128, NOUT=64):  h1 update
__device__ __forceinline__ float fsig(float x)  { return 1.f / (1.f + __expf(-x)); }
__device__ __forceinline__ float ftanh(float x) { return 2.f / (1.f + __expf(-2.f * x)) - 1.f; }

template<int MODE>
__global__ void __launch_bounds__(256) k_fused(const float* __restrict__ W,
                                               const float* __restrict__ B, int t) {
    constexpr int  K    = (MODE < 2) ? 72 : 128;
    constexpr int  KP   = (MODE < 2) ? 96 : 128;   // padded to multiple of 32
    constexpr bool GATE = (MODE == 0 || MODE == 2);
    constexpr int  NOUT = GATE ? 128 : 64;
    constexpr int  LDA  = 66;                      // 64 + pad (8B-aligned pairs)
    extern __shared__ float sm[];
    float* As = sm;                                // [KP][LDA] transposed A tile
    float* Ws = sm + KP * LDA;                     // [32][64] streamed W tile

    int tid  = threadIdx.x;
    int lane = tid & 31;
    int wid  = tid >> 5;
    float* __restrict__ h = (MODE < 2) ? g_h0 : g_h1;

    // zero the K..KP pad rows once (GEMM reads them in the last K-tile)
    if (KP > K) {
        for (int i = tid; i < (KP - K) * LDA; i += 256) As[K * LDA + i] = 0.f;
        __syncthreads();
    }

    for (int tb = 0; tb < 2; tb++) {
        int tile = blockIdx.x + tb * GRID_F;
        if (tile >= NTILES) break;
        int rowBlock = tile * 64;

        // ---- gather phase: warp per node, 8 nodes per warp ----
        for (int rr = 0; rr < 8; rr++) {
            int r = wid * 8 + rr;
            int n = rowBlock + r;
            if (n >= NN) continue;
            int s0 = g_rowstart[n], s1 = g_rowstart[n + 1];
            if (MODE == 0 || MODE == 1) {
                const float* __restrict__ feat = (MODE == 0) ? g_h0 : g_rh;
                float a0 = 0.f, a1 = 0.f;
                #pragma unroll 4
                for (int e = s0; e < s1; e++) {
                    int2 ed = g_edge[e];
                    float w = __int_as_float(ed.y);
                    float2 v = *reinterpret_cast<const float2*>(feat + (size_t)ed.x * 64 + 2 * lane);
                    a0 += w * v.x; a1 += w * v.y;
                }
                As[(8 + 2 * lane) * LDA + r] = a0;
                As[(9 + 2 * lane) * LDA + r] = a1;
                if (lane < 8) As[lane * LDA + r] = g_aggx[(size_t)n * 96 + lane * 12 + t];
            } else if (MODE == 2) {
                float a0 = 0.f, a1 = 0.f, a2 = 0.f, a3 = 0.f;
                #pragma unroll 4
                for (int e = s0; e < s1; e++) {
                    int2 ed = g_edge[e];
                    float w = __int_as_float(ed.y);
                    float2 v0 = *reinterpret_cast<const float2*>(g_h0 + (size_t)ed.x * 64 + 2 * lane);
                    float2 v1 = *reinterpret_cast<const float2*>(g_h1 + (size_t)ed.x * 64 + 2 * lane);
                    a0 += w * v0.x; a1 += w * v0.y;
                    a2 += w * v1.x; a3 += w * v1.y;
                }
                As[(2 * lane)      * LDA + r] = a0;
                As[(2 * lane + 1)  * LDA + r] = a1;
                As[(64 + 2 * lane) * LDA + r] = a2;
                As[(65 + 2 * lane) * LDA + r] = a3;
                *reinterpret_cast<float2*>(g_aggh0 + (size_t)n * 64 + 2 * lane) = make_float2(a0, a1);
            } else { // MODE 3
                float2 c = *reinterpret_cast<const float2*>(g_aggh0 + (size_t)n * 64 + 2 * lane);
                As[(2 * lane)     * LDA + r] = c.x;
                As[(2 * lane + 1) * LDA + r] = c.y;
                float a0 = 0.f, a1 = 0.f;
                #pragma unroll 4
                for (int e = s0; e < s1; e++) {
                    int2 ed = g_edge[e];
                    float w = __int_as_float(ed.y);
                    float2 v = *reinterpret_cast<const float2*>(g_rh + (size_t)ed.x * 64 + 2 * lane);
                    a0 += w * v.x; a1 += w * v.y;
                }
                As[(64 + 2 * lane) * LDA + r] = a0;
                As[(65 + 2 * lane) * LDA + r] = a1;
            }
        }
        __syncthreads();

        // ---- GEMM phase: 64x64(/128) tile, thread tile 4x4 ----
        int rg = tid >> 4, cg = tid & 15;
        int r0 = rg * 4, c0 = cg * 4;
        constexpr int NY = GATE ? 2 : 1;

        for (int ycol = 0; ycol < NY; ycol++) {
            int colBlock = ycol * 64;
            unsigned long long acc[2][4];
            #pragma unroll
            for (int p = 0; p < 2; p++)
                #pragma unroll
                for (int q = 0; q < 4; q++) acc[p][q] = 0ull;

            for (int kc = 0; kc < KP; kc += 32) {
                #pragma unroll
                for (int l = 0; l < 8; l++) {
                    int idx = tid + l * 256;          // 0..2047
                    int kk = idx >> 6, j = idx & 63;
                    int gk = kc + kk;
                    Ws[kk * 64 + j] = (gk < K) ? W[(size_t)gk * NOUT + colBlock + j] : 0.f;
                }
                __syncthreads();
                #pragma unroll
                for (int kk = 0; kk < 32; kk++) {
                    float4 b = *reinterpret_cast<const float4*>(&Ws[kk * 64 + c0]);
                    unsigned long long bd[4];
                    asm("mov.b64 %0,{%1,%1};" : "=l"(bd[0]) : "f"(b.x));
                    asm("mov.b64 %0,{%1,%1};" : "=l"(bd[1]) : "f"(b.y));
                    asm("mov.b64 %0,{%1,%1};" : "=l"(bd[2]) : "f"(b.z));
                    asm("mov.b64 %0,{%1,%1};" : "=l"(bd[3]) : "f"(b.w));
                    unsigned long long ap[2];
                    #pragma unroll
                    for (int p = 0; p < 2; p++)
                        ap[p] = *reinterpret_cast<const unsigned long long*>(
                            &As[(kc + kk) * LDA + r0 + 2 * p]);
                    #pragma unroll
                    for (int p = 0; p < 2; p++)
                        #pragma unroll
                        for (int q = 0; q < 4; q++)
                            asm("fma.rn.f32x2 %0,%1,%2,%0;" : "+l"(acc[p][q]) : "l"(ap[p]), "l"(bd[q]));
                }
                __syncthreads();
            }

            float bias[4];
            #pragma unroll
            for (int q = 0; q < 4; q++) bias[q] = B[colBlock + c0 + q];

            #pragma unroll
            for (int p = 0; p < 2; p++) {
                float vlo[4], vhi[4];
                #pragma unroll
                for (int q = 0; q < 4; q++)
                    asm("mov.b64 {%0,%1},%2;" : "=f"(vlo[q]), "=f"(vhi[q]) : "l"(acc[p][q]));
                #pragma unroll
                for (int hp = 0; hp < 2; hp++) {
                    int n = rowBlock + r0 + 2 * p + hp;
                    if (n >= NN) continue;
                    float v[4];
                    #pragma unroll
                    for (int q = 0; q < 4; q++) v[q] = (hp ? vhi[q] : vlo[q]) + bias[q];
                    if (GATE) {
                        if (ycol == 0) {
                            float4 h4 = *reinterpret_cast<const float4*>(&h[(size_t)n * 64 + c0]);
                            float4 o = make_float4(fsig(v[0]) * h4.x, fsig(v[1]) * h4.y,
                                                   fsig(v[2]) * h4.z, fsig(v[3]) * h4.w);
                            *reinterpret_cast<float4*>(&g_rh[(size_t)n * 64 + c0]) = o;
                        } else {
                            float4 o = make_float4(fsig(v[0]), fsig(v[1]), fsig(v[2]), fsig(v[3]));
                            *reinterpret_cast<float4*>(&g_z[(size_t)n * 64 + c0]) = o;
                        }
                    } else {
                        float4 z4 = *reinterpret_cast<const float4*>(&g_z[(size_t)n * 64 + c0]);
                        float4 h4 = *reinterpret_cast<const float4*>(&h[(size_t)n * 64 + c0]);
                        float4 o = make_float4(z4.x * h4.x + (1.f - z4.x) * ftanh(v[0]),
                                               z4.y * h4.y + (1.f - z4.y) * ftanh(v[1]),
                                               z4.z * h4.z + (1.f - z4.z) * ftanh(v[2]),
                                               z4.w * h4.w + (1.f - z4.w) * ftanh(v[3]));
                        *reinterpret_cast<float4*>(&h[(size_t)n * 64 + c0]) = o;
                    }
                }
            }
        }
        if (tb == 0) __syncthreads();   // As reused by next tile
    }
}

// ---------------- output head ----------------
__global__ void k_out(const float* __restrict__ Wout, const float* __restrict__ bout,
                      float* __restrict__ out) {
    int n = (blockIdx.x * blockDim.x + threadIdx.x) >> 5;
    int lane = threadIdx.x & 31;
    if (n >= NN) return;
    const float* hp = g_h1 + (size_t)n * 64;
    float s = hp[lane] * Wout[lane] + hp[lane + 32] * Wout[lane + 32];
    #pragma unroll
    for (int off = 16; off > 0; off >>= 1)
        s += __shfl_down_sync(0xffffffffu, s, off);
    if (lane == 0) out[n] = s + bout[0];
}

// ---------------- host launcher ----------------
extern "C" void kernel_launch(void* const* d_in, const int* in_sizes, int n_in,
                              void* d_out, int out_size) {
    const float* x    = (const float*)d_in[0];
    const int*   ei   = (const int*)  d_in[1];
    const float* ew   = (const float*)d_in[2];
    const float* Wg0  = (const float*)d_in[3];
    const float* bg0  = (const float*)d_in[4];
    const float* Wc0  = (const float*)d_in[5];
    const float* bc0  = (const float*)d_in[6];
    const float* Wg1  = (const float*)d_in[7];
    const float* bg1  = (const float*)d_in[8];
    const float* Wc1  = (const float*)d_in[9];
    const float* bc1  = (const float*)d_in[10];
    const float* Wout = (const float*)d_in[11];
    const float* bout = (const float*)d_in[12];

    int E = in_sizes[1] / 2;
    if (E > NE) E = NE;
    const int* src = ei;
    const int* dst = ei + E;

    const int SMEM_L0 = (96 * 66 + 32 * 64) * 4;    // 33536 B -> ~6 blocks/SM
    const int SMEM_L1 = (128 * 66 + 32 * 64) * 4;   // 41984 B -> ~5 blocks/SM
    cudaFuncSetAttribute(k_fused<0>, cudaFuncAttributeMaxDynamicSharedMemorySize, SMEM_L0);
    cudaFuncSetAttribute(k_fused<1>, cudaFuncAttributeMaxDynamicSharedMemorySize, SMEM_L0);
    cudaFuncSetAttribute(k_fused<2>, cudaFuncAttributeMaxDynamicSharedMemorySize, SMEM_L1);
    cudaFuncSetAttribute(k_fused<3>, cudaFuncAttributeMaxDynamicSharedMemorySize, SMEM_L1);

    {
        size_t tot = (size_t)NN * 64;
        k_init<<<(int)((tot + 255) / 256), 256>>>();
    }
    k_count<<<(E + 255) / 256, 256>>>(dst, E);
    k_scan<<<1, 1024>>>();
    k_scatter<<<(E + 255) / 256, 256>>>(src, dst, ew, E);

    const int AGG_BLOCKS = (NN + 7) / 8;
    k_aggx<<<AGG_BLOCKS, 256>>>(x);

    for (int t = 0; t < 12; t++) {
        k_fused<0><<<GRID_F, 256, SMEM_L0>>>(Wg0, bg0, t);
        k_fused<1><<<GRID_F, 256, SMEM_L0>>>(Wc0, bc0, t);
        k_fused<2><<<GRID_F, 256, SMEM_L1>>>(Wg1, bg1, t);
        k_fused<3><<<GRID_F, 256, SMEM_L1>>>(Wc1, bc1, t);
    }

    k_out<<<AGG_BLOCKS, 256>>>(Wout, bout, (float*)d_out);
}